// round 15
// baseline (speedup 1.0000x reference)
#include <cuda_runtime.h>
#include <cuda_bf16.h>
#include <cstdint>
#include <cmath>

#define Bq 4
#define Lq 512
#define Dq 768
#define Hq 12
#define DHq 64
#define Rq 128
#define Mq (Bq*Lq)          // 2048
#define threeD (3*Dq)       // 2304
#define NC 8                // scan chunks
#define CL 64               // tokens per chunk
#define PI_F 3.14159265358979323846f

// ---------------- scratch (static __device__ — no allocation) ----------------
__device__ float  g_qkv  [Mq*threeD];
__device__ float4 g_gp   [Mq*Hq];
__device__ float  g_gate_dummy[Mq*Hq];

__device__ float4 g_sc [Bq*Hq*Lq];
__device__ float  g_C  [Bq*Hq*NC*DHq*DHq];
__device__ float  g_zC [Bq*Hq*NC*DHq];

__device__ __align__(16) __nv_bfloat16 g_xnhi[Mq*Dq],      g_xnlo[Mq*Dq];
__device__ __align__(16) __nv_bfloat16 g_wqThi[threeD*Dq], g_wqTlo[threeD*Dq];
__device__ __align__(16) __nv_bfloat16 g_wpThi[Dq*Dq],     g_wpTlo[Dq*Dq];
__device__ __align__(16) __nv_bfloat16 g_athi[Mq*Dq],      g_atlo[Mq*Dq];

__device__ __align__(16) float g_lng[Dq], g_lnb[Dq], g_bproj[Dq];
__device__ __align__(16) float g_memg[DHq], g_memb[DHq];

static __device__ __forceinline__ float sigmoidf_(float x){ return 1.f/(1.f+expf(-x)); }

static __device__ __forceinline__ uint32_t smem_u32(const void* p){
    uint32_t a;
    asm("{ .reg .u64 t; cvta.to.shared.u64 t, %1; cvt.u32.u64 %0, t; }" : "=r"(a) : "l"(p));
    return a;
}
static __device__ __forceinline__ void ldsm_x4(uint32_t addr, uint32_t* r){
    asm volatile("ldmatrix.sync.aligned.m8n8.x4.shared.b16 {%0,%1,%2,%3}, [%4];"
        : "=r"(r[0]), "=r"(r[1]), "=r"(r[2]), "=r"(r[3]) : "r"(addr));
}
static __device__ __forceinline__ void mma16816(float* d, const uint32_t* a, const uint32_t* b){
    asm volatile("mma.sync.aligned.m16n8k16.row.col.f32.bf16.bf16.f32 "
        "{%0,%1,%2,%3}, {%4,%5,%6,%7}, {%8,%9}, {%0,%1,%2,%3};"
        : "+f"(d[0]), "+f"(d[1]), "+f"(d[2]), "+f"(d[3])
        : "r"(a[0]), "r"(a[1]), "r"(a[2]), "r"(a[3]), "r"(b[0]), "r"(b[1]));
}

// ---------------- K0: route same-size parameter groups by value ----------------
__global__ void route_params_kernel(const float* __restrict__ a0,
                                    const float* __restrict__ a1,
                                    const float* __restrict__ a2,
                                    const float* __restrict__ c0,
                                    const float* __restrict__ c1)
{
    int t = threadIdx.x;
    __shared__ float red[256];
    __shared__ float dev[3], dev64[2];
    const float* arr[3] = {a0, a1, a2};
    for (int j = 0; j < 3; j++){
        float s = 0.f;
        for (int i = t; i < Dq; i += 256) s += fabsf(arr[j][i] - 1.f);
        red[t] = s; __syncthreads();
        for (int o = 128; o > 0; o >>= 1){ if (t < o) red[t] += red[t+o]; __syncthreads(); }
        if (t == 0) dev[j] = red[0];
        __syncthreads();
    }
    const float* brr[2] = {c0, c1};
    for (int j = 0; j < 2; j++){
        float s = 0.f;
        for (int i = t; i < DHq; i += 256) s += fabsf(brr[j][i] - 1.f);
        red[t] = s; __syncthreads();
        for (int o = 128; o > 0; o >>= 1){ if (t < o) red[t] += red[t+o]; __syncthreads(); }
        if (t == 0) dev64[j] = red[0];
        __syncthreads();
    }
    int gi = (dev[0] <= dev[1] && dev[0] <= dev[2]) ? 0 : ((dev[1] <= dev[2]) ? 1 : 2);
    int r0 = (gi == 0) ? 1 : 0;
    int r1 = (gi == 2) ? 1 : 2;
    for (int i = t; i < Dq; i += 256){
        g_lng[i]   = arr[gi][i];
        g_bproj[i] = arr[r0][i];
        g_lnb[i]   = arr[r1][i];
    }
    int mg = (dev64[0] <= dev64[1]) ? 0 : 1;
    for (int i = t; i < DHq; i += 256){
        g_memg[i] = brr[mg][i];
        g_memb[i] = brr[1-mg][i];
    }
}

// ---------------- K1: LN over 768, x cached in regs, bf16 hi/lo split out ----------------
__global__ void ln768_split(const float* __restrict__ x,
                            const float* __restrict__ g,
                            const float* __restrict__ b,
                            __nv_bfloat16* __restrict__ yhi,
                            __nv_bfloat16* __restrict__ ylo)
{
    int m = blockIdx.x;
    int t = threadIdx.x;  // 256
    __shared__ float sbuf[256];
    __shared__ float s_mu, s_rstd;
    const float* xr = x + (size_t)m*Dq;
    float v[3];
    float s = 0.f;
#pragma unroll
    for (int i=0;i<3;i++){ v[i] = xr[t + 256*i]; s += v[i]; }
    sbuf[t]=s; __syncthreads();
    for (int o=128;o>0;o>>=1){ if(t<o) sbuf[t]+=sbuf[t+o]; __syncthreads(); }
    if (t==0) s_mu = sbuf[0]*(1.f/Dq);
    __syncthreads();
    float mu = s_mu;
    float vv = 0.f;
#pragma unroll
    for (int i=0;i<3;i++){ float d=v[i]-mu; vv += d*d; }
    sbuf[t]=vv; __syncthreads();
    for (int o=128;o>0;o>>=1){ if(t<o) sbuf[t]+=sbuf[t+o]; __syncthreads(); }
    if (t==0) s_rstd = rsqrtf(sbuf[0]*(1.f/Dq) + 1e-5f);
    __syncthreads();
    float rstd = s_rstd;
#pragma unroll
    for (int i=0;i<3;i++){
        int idx = t + 256*i;
        float y = (v[i]-mu)*rstd*g[idx] + b[idx];
        __nv_bfloat16 hi = __float2bfloat16(y);
        __nv_bfloat16 lo = __float2bfloat16(y - __bfloat162float(hi));
        yhi[(size_t)m*Dq + idx] = hi;
        ylo[(size_t)m*Dq + idx] = lo;
    }
}

// ---------------- K1b: merged transpose+split for Wqkv and Wproj ----------------
__global__ void wsplitT2(const float* __restrict__ Wq, const float* __restrict__ Wp,
                         __nv_bfloat16* __restrict__ hiQ, __nv_bfloat16* __restrict__ loQ,
                         __nv_bfloat16* __restrict__ hiP, __nv_bfloat16* __restrict__ loP)
{
    __shared__ float t[32][33];
    int bx = blockIdx.x;
    const float* W; __nv_bfloat16 *Th, *Tl; int N, n0;
    if (bx < 72){ W = Wq; Th = hiQ; Tl = loQ; N = threeD; n0 = bx*32; }
    else        { W = Wp; Th = hiP; Tl = loP; N = Dq;     n0 = (bx-72)*32; }
    int k0 = blockIdx.y*32;
    int tx = threadIdx.x, ty = threadIdx.y;
#pragma unroll
    for (int j=0;j<4;j++){
        int k = k0 + ty + j*8;
        t[ty + j*8][tx] = W[(size_t)k*N + n0 + tx];
    }
    __syncthreads();
#pragma unroll
    for (int j=0;j<4;j++){
        int n = n0 + ty + j*8;
        float v = t[tx][ty + j*8];
        __nv_bfloat16 hi = __float2bfloat16(v);
        __nv_bfloat16 lo = __float2bfloat16(v - __bfloat162float(hi));
        Th[(size_t)n*Dq + k0 + tx] = hi;
        Tl[(size_t)n*Dq + k0 + tx] = lo;
    }
}

// ---------------- K2: HMMA combo GEMM, 512 threads, warp tile 32x32 (round-14) ----------------
__global__ __launch_bounds__(512) void hmma_gemm_combo(
    const __nv_bfloat16* __restrict__ Ahi, const __nv_bfloat16* __restrict__ Alo,
    const __nv_bfloat16* __restrict__ BhiT, const __nv_bfloat16* __restrict__ BloT,
    const float* __restrict__ bias, float* __restrict__ C,
    int Nn, int Kn, int eluCols)
{
    extern __shared__ __align__(16) __nv_bfloat16 dsm[];
    int tid = threadIdx.x, lane = tid&31, wid = tid>>5;
    int warp_m = wid & 3, warp_n = wid >> 2;
    int m0 = blockIdx.y*128, n0 = blockIdx.x*128;

    float acc[2][4][4];
#pragma unroll
    for (int i=0;i<2;i++)
#pragma unroll
        for (int j=0;j<4;j++)
#pragma unroll
            for (int q=0;q<4;q++) acc[i][j][q]=0.f;

    int kslabs = Kn/32;
    int srow = tid>>2, ssub = tid&3;

    const __nv_bfloat16* gAh = Ahi  + (size_t)(m0+srow)*Kn + ssub*8;
    const __nv_bfloat16* gAl = Alo  + (size_t)(m0+srow)*Kn + ssub*8;
    const __nv_bfloat16* gBh = BhiT + (size_t)(n0+srow)*Kn + ssub*8;
    const __nv_bfloat16* gBl = BloT + (size_t)(n0+srow)*Kn + ssub*8;

    uint4 pah = *(const uint4*)gAh;
    uint4 pal = *(const uint4*)gAl;
    uint4 pbh = *(const uint4*)gBh;
    uint4 pbl = *(const uint4*)gBl;

    int r7 = lane & 7, sel = lane >> 3;
    int soff = srow*40 + ssub*8;

    for (int s=0; s<kslabs; s++){
        int buf = s & 1;
        __nv_bfloat16* bb = dsm + buf*20480;
        *(uint4*)(bb + soff)         = pah;
        *(uint4*)(bb + 5120  + soff) = pal;
        *(uint4*)(bb + 10240 + soff) = pbh;
        *(uint4*)(bb + 15360 + soff) = pbl;
        __syncthreads();

        if (s+1 < kslabs){
            int kk = (s+1)*32;
            pah = *(const uint4*)(gAh + kk);
            pal = *(const uint4*)(gAl + kk);
            pbh = *(const uint4*)(gBh + kk);
            pbl = *(const uint4*)(gBl + kk);
        }

        __nv_bfloat16* sAh = bb;
        __nv_bfloat16* sAl = bb + 5120;
        __nv_bfloat16* sBh = bb + 10240;
        __nv_bfloat16* sBl = bb + 15360;

#pragma unroll
        for (int ks=0; ks<2; ks++){
            uint32_t aF[2][4], bFh[2][4], bFl[2][4];
            int acol = ks*16 + ((sel>>1)<<3);
            int bcol = ks*16 + ((sel&1)<<3);
#pragma unroll
            for (int am=0; am<2; am++){
                int row = warp_m*32 + am*16 + r7 + ((sel&1)<<3);
                ldsm_x4(smem_u32(sAh + row*40 + acol), aF[am]);
            }
#pragma unroll
            for (int p=0; p<2; p++){
                int row = warp_n*32 + p*16 + r7 + ((sel>>1)<<3);
                ldsm_x4(smem_u32(sBh + row*40 + bcol), bFh[p]);
                ldsm_x4(smem_u32(sBl + row*40 + bcol), bFl[p]);
            }
#pragma unroll
            for (int am=0; am<2; am++)
#pragma unroll
                for (int an=0; an<4; an++){
                    mma16816(acc[am][an], aF[am], &bFh[an>>1][(an&1)*2]);
                    mma16816(acc[am][an], aF[am], &bFl[an>>1][(an&1)*2]);
                }
#pragma unroll
            for (int am=0; am<2; am++){
                int row = warp_m*32 + am*16 + r7 + ((sel&1)<<3);
                ldsm_x4(smem_u32(sAl + row*40 + acol), aF[am]);
            }
#pragma unroll
            for (int am=0; am<2; am++)
#pragma unroll
                for (int an=0; an<4; an++)
                    mma16816(acc[am][an], aF[am], &bFh[an>>1][(an&1)*2]);
        }
    }

    int g = lane>>2, t4 = lane&3;
#pragma unroll
    for (int am=0; am<2; am++){
#pragma unroll
        for (int an=0; an<4; an++){
            int row = m0 + warp_m*32 + am*16 + g;
            int col = n0 + warp_n*32 + an*8 + t4*2;
            float b0 = bias[col], b1 = bias[col+1];
            float v0 = acc[am][an][0] + b0;
            float v1 = acc[am][an][1] + b1;
            float v2 = acc[am][an][2] + b0;
            float v3 = acc[am][an][3] + b1;
            if (col   < eluCols){ v0 = (v0>0.f)?(v0+1.f):expf(v0); v2 = (v2>0.f)?(v2+1.f):expf(v2); }
            if (col+1 < eluCols){ v1 = (v1>0.f)?(v1+1.f):expf(v1); v3 = (v3>0.f)?(v3+1.f):expf(v3); }
            *(float2*)(C + (size_t)row*Nn + col)     = make_float2(v0, v1);
            *(float2*)(C + (size_t)(row+8)*Nn + col) = make_float2(v2, v3);
        }
    }
}

// ---------------- K3: bottleneck, thread owns (token, 4 W1 cols) ----------------
__global__ __launch_bounds__(256) void bottleneck8(
    const float* __restrict__ x,  const float* __restrict__ W1,
    const float* __restrict__ W2, const float* __restrict__ T,
    float4* __restrict__ gp, float* __restrict__ gate_out)
{
    int m0 = blockIdx.x*8;
    int t = threadIdx.x;
    int tok = t >> 5, lane = t & 31;
    __shared__ float sx[8][Dq];
    __shared__ float sh[8][Rq];
    __shared__ float sp[8][Hq*5];

    const float* xr = x + (size_t)m0*Dq;
    float* sxf = &sx[0][0];
    for (int i=t; i<8*Dq; i+=256) sxf[i] = xr[i];
    __syncthreads();

    float a0=0.f, a1=0.f, a2=0.f, a3=0.f;
    const float4* w1v = (const float4*)W1;
    for (int k=0;k<Dq;k++){
        float xv = sx[tok][k];
        float4 w = w1v[(size_t)k*32 + lane];
        a0 = fmaf(xv, w.x, a0);
        a1 = fmaf(xv, w.y, a1);
        a2 = fmaf(xv, w.z, a2);
        a3 = fmaf(xv, w.w, a3);
    }
    int c0 = lane*4;
    sh[tok][c0+0] = a0*sigmoidf_(a0);
    sh[tok][c0+1] = a1*sigmoidf_(a1);
    sh[tok][c0+2] = a2*sigmoidf_(a2);
    sh[tok][c0+3] = a3*sigmoidf_(a3);
    __syncthreads();

    if (t < 240){
        int c = t % 60;
        int tb = (t/60)*2;
#pragma unroll
        for (int tt=0; tt<2; tt++){
            float a = 0.f;
            for (int j=0;j<Rq;j++) a = fmaf(sh[tb+tt][j], W2[(size_t)j*(Hq*5) + c], a);
            sp[tb+tt][c] = a;
        }
    }
    __syncthreads();

    if (t < 8*Hq){
        int tk = t / Hq, hh = t % Hq;
        float p0=sp[tk][hh*5+0], p1=sp[tk][hh*5+1], p2=sp[tk][hh*5+2];
        float p3=sp[tk][hh*5+3], p4=sp[tk][hh*5+4];
        float temp = fminf(fmaxf(T[0], 0.1f), 2.0f);
        float sem_amp = sigmoidf_(p0);
        float sem_ph  = tanhf(p1)*PI_F;
        float ctx_amp = sigmoidf_(p2);
        float ctx_ph  = tanhf(p3)*PI_F;
        float decay   = 0.5f + 0.49f*sigmoidf_(p4);
        float inter   = tanhf(sem_amp*ctx_amp*cosf(sem_ph - ctx_ph)) * temp;
        float gate    = sigmoidf_(inter);
        float ema     = 1.f - decay;
        float ld      = logf(decay + 1e-8f);
        gp[(size_t)(m0+tk)*Hq + hh] = make_float4((1.f+gate)*ema, ema, ld, 0.f);
        gate_out[(size_t)(m0+tk)*Hq + hh] = gate;
    }
}

// ---------------- P0: per-(b,h) cumulative log-decay (fp64 block scan) ----------------
__global__ __launch_bounds__(512) void scan_pre(
    const float4* __restrict__ gp, float4* __restrict__ sc)
{
    int bh = blockIdx.x;
    int b = bh / Hq, h = bh % Hq;
    int l = threadIdx.x;
    __shared__ double scs[Lq];
    float4 gv = gp[(size_t)(b*Lq + l)*Hq + h];
    scs[l] = (double)gv.z;
    __syncthreads();
    for (int o=1;o<Lq;o<<=1){
        double add = (l>=o) ? scs[l-o] : 0.0;
        __syncthreads();
        scs[l] += add;
        __syncthreads();
    }
    double cld = scs[l];
    if (cld < -85.0) cld = -85.0;
    float df  = expf((float)cld);
    float idf = expf((float)(-cld));
    sc[(size_t)bh*Lq + l] = make_float4(gv.x*idf, gv.y*idf, df, 0.f);
}

// ---------------- P1: chunk-local kv/z accumulation ----------------
__global__ __launch_bounds__(256) void scan_chunk_acc(
    const float* __restrict__ qkv, const float4* __restrict__ sc,
    float* __restrict__ Cbuf, float* __restrict__ zbuf)
{
    int blk = blockIdx.x;
    int bh = blk >> 3, c = blk & 7;
    int b = bh / Hq, h = bh % Hq;
    int t = threadIdx.x, g = t>>6, e = t&63;
    int l0 = c*CL;

    __shared__ float sk[2][2][64], sv[2][2][64];

    float kv[16];
#pragma unroll
    for (int i=0;i<16;i++) kv[i]=0.f;
    float z = 0.f;

    int sel = t >> 6, ee = t & 63;
    for (int it=0; it<CL/2; it++){
        int buf = it & 1;
        int l = l0 + it*2;
        {
            size_t base = ((size_t)(b*Lq + l + (sel&1)))*threeD + h*DHq;
            if (sel < 2) sk[buf][sel][ee]   = qkv[base + Dq   + ee];
            else         sv[buf][sel-2][ee] = qkv[base + 2*Dq + ee];
        }
        float4 s0 = sc[(size_t)bh*Lq + l];
        float4 s1 = sc[(size_t)bh*Lq + l+1];
        __syncthreads();
        float w0 = s0.x * sv[buf][0][e];
        float w1 = s1.x * sv[buf][1][e];
#pragma unroll
        for (int i=0;i<16;i++){
            int d = g*16 + i;
            kv[i] = fmaf(sk[buf][0][d], w0, kv[i]);
            kv[i] = fmaf(sk[buf][1][d], w1, kv[i]);
        }
        if (t < 64){
            z = fmaf(sk[buf][0][t], s0.y, z);
            z = fmaf(sk[buf][1][t], s1.y, z);
        }
    }
    float* Cp = Cbuf + (size_t)blk*(DHq*DHq);
#pragma unroll
    for (int i=0;i<16;i++) Cp[(g*16+i)*64 + e] = kv[i];
    if (t < 64) zbuf[(size_t)blk*DHq + t] = z;
}

// ---------------- P2: exclusive prefix over chunks (in place) ----------------
__global__ __launch_bounds__(256) void scan_prefix(
    float* __restrict__ Cbuf, float* __restrict__ zbuf)
{
    int bh = blockIdx.x;
    int t = threadIdx.x;
#pragma unroll
    for (int j=0;j<16;j++){
        int idx = j*256 + t;
        float run = 0.f;
#pragma unroll
        for (int c=0;c<NC;c++){
            float* p = Cbuf + ((size_t)(bh*NC + c))*(DHq*DHq) + idx;
            float v = *p; *p = run; run += v;
        }
    }
    if (t < 64){
        float run = 0.f;
#pragma unroll
        for (int c=0;c<NC;c++){
            float* p = zbuf + ((size_t)(bh*NC + c))*DHq + t;
            float v = *p; *p = run; run += v;
        }
    }
}

// ---------------- P3: chunk replay + q readout + FUSED mem-LN -> bf16 split ----------------
__global__ __launch_bounds__(256) void scan_chunk_out_ln(
    const float* __restrict__ qkv, const float4* __restrict__ sc,
    const float* __restrict__ Cbuf, const float* __restrict__ zbuf,
    const float* __restrict__ lg, const float* __restrict__ lb,
    __nv_bfloat16* __restrict__ yhi, __nv_bfloat16* __restrict__ ylo)
{
    int blk = blockIdx.x;
    int bh = blk >> 3, c = blk & 7;
    int b = bh / Hq, h = bh % Hq;
    int t = threadIdx.x, g = t>>6, e = t&63;
    int sec = t >> 6;
    int l0 = c*CL;

    __shared__ float sq[2][64], sk[2][64], sv[2][64];
    __shared__ float spart[2][4][64];
    __shared__ float sden[2][4][4];

    float kv[16];
    const float* Cp = Cbuf + (size_t)blk*(DHq*DHq);
#pragma unroll
    for (int i=0;i<16;i++) kv[i] = Cp[(g*16+i)*64 + e];
    float z[4];
    if (e < 4){
        int d0 = g*16 + e*4;
#pragma unroll
        for (int i=0;i<4;i++) z[i] = zbuf[(size_t)blk*DHq + d0 + i];
    } else {
#pragma unroll
        for (int i=0;i<4;i++) z[i] = 0.f;
    }

    float preA = 0.f, preB = 0.f;
    {
        size_t b0 = ((size_t)(b*Lq + l0  ))*threeD + h*DHq;
        size_t b1 = ((size_t)(b*Lq + l0+1))*threeD + h*DHq;
        if (t < 192){ preA = qkv[b0 + (size_t)sec*Dq + e]; preB = qkv[b1 + (size_t)sec*Dq + e]; }
    }
    float4 scA = sc[(size_t)bh*Lq + l0];
    float4 scB = sc[(size_t)bh*Lq + l0+1];

    for (int l=l0; l<l0+CL; l+=2){
        if      (t <  64){ sq[0][e] = preA; sq[1][e] = preB; }
        else if (t < 128){ sk[0][e] = preA; sk[1][e] = preB; }
        else if (t < 192){ sv[0][e] = preA; sv[1][e] = preB; }
        float wkA = scA.x, wzA = scA.y, dfA = scA.z;
        float wkB = scB.x, wzB = scB.y, dfB = scB.z;
        __syncthreads();                 // bar1

        if (l+2 < l0+CL){
            size_t bn0 = ((size_t)(b*Lq + l+2))*threeD + h*DHq;
            size_t bn1 = ((size_t)(b*Lq + l+3))*threeD + h*DHq;
            if (t < 192){ preA = qkv[bn0 + (size_t)sec*Dq + e]; preB = qkv[bn1 + (size_t)sec*Dq + e]; }
            scA = sc[(size_t)bh*Lq + l+2];
            scB = sc[(size_t)bh*Lq + l+3];
        }

        {
            float kvw = wkA * sv[0][e];
            float num = 0.f;
#pragma unroll
            for (int i=0;i<16;i++){
                int d = g*16 + i;
                kv[i] = fmaf(sk[0][d], kvw, kv[i]);
                num   = fmaf(sq[0][d], kv[i]*dfA, num);
            }
            spart[0][g][e] = num;
        }
        {
            float kvw = wkB * sv[1][e];
            float num = 0.f;
#pragma unroll
            for (int i=0;i<16;i++){
                int d = g*16 + i;
                kv[i] = fmaf(sk[1][d], kvw, kv[i]);
                num   = fmaf(sq[1][d], kv[i]*dfB, num);
            }
            spart[1][g][e] = num;
        }
        if (e < 4){
            int d0 = g*16 + e*4;
            float dA = 0.f, dB = 0.f;
#pragma unroll
            for (int i=0;i<4;i++){
                z[i] = fmaf(sk[0][d0+i], wzA, z[i]);
                dA   = fmaf(sq[0][d0+i], z[i]*dfA, dA);
            }
#pragma unroll
            for (int i=0;i<4;i++){
                z[i] = fmaf(sk[1][d0+i], wzB, z[i]);
                dB   = fmaf(sq[1][d0+i], z[i]*dfB, dB);
            }
            sden[0][g][e] = dA;
            sden[1][g][e] = dB;
        }
        __syncthreads();                 // bar2

        if (t < 64){
            int w = t >> 5;
            int lane = t & 31;
            float den = 1e-6f;
#pragma unroll
            for (int gg=0;gg<4;gg++)
#pragma unroll
                for (int jj=0;jj<4;jj++) den += sden[w][gg][jj];
            float y0 = (spart[w][0][lane]    + spart[w][1][lane]    + spart[w][2][lane]    + spart[w][3][lane])    / den;
            float y1 = (spart[w][0][lane+32] + spart[w][1][lane+32] + spart[w][2][lane+32] + spart[w][3][lane+32]) / den;
            float s = y0 + y1;
#pragma unroll
            for (int o=16;o>0;o>>=1) s += __shfl_xor_sync(0xffffffffu, s, o);
            float mu = s*(1.f/DHq);
            float d0 = y0-mu, d1 = y1-mu;
            float vv = d0*d0 + d1*d1;
#pragma unroll
            for (int o=16;o>0;o>>=1) vv += __shfl_xor_sync(0xffffffffu, vv, o);
            float rstd = rsqrtf(vv*(1.f/DHq) + 1e-5f);
            float o0 = d0*rstd*lg[lane]    + lb[lane];
            float o1 = d1*rstd*lg[lane+32] + lb[lane+32];
            size_t row = ((size_t)(b*Lq + l + w)*Hq + h)*DHq;
            __nv_bfloat16 h0 = __float2bfloat16(o0);
            __nv_bfloat16 h1 = __float2bfloat16(o1);
            yhi[row + lane]    = h0;
            yhi[row + lane+32] = h1;
            ylo[row + lane]    = __float2bfloat16(o0 - __bfloat162float(h0));
            ylo[row + lane+32] = __float2bfloat16(o1 - __bfloat162float(h1));
        }
    }
}

// ---------------- launch (multi-stream fork/join, graph-capturable) ----------------
extern "C" void kernel_launch(void* const* d_in, const int* in_sizes, int n_in,
                              void* d_out, int out_size)
{
    const float* x=nullptr; const float* Wqkv=nullptr; const float* bqkv=nullptr;
    const float* Wb1=nullptr; const float* Wb2=nullptr; const float* temp=nullptr;
    const float* Wproj=nullptr;
    const float* p768[3]={nullptr,nullptr,nullptr}; int n768=0;
    const float* p64[2]={nullptr,nullptr};          int n64=0;

    for (int pass=0; pass<2; pass++){
        int div = (pass==0) ? 1 : 4;
        n768=0; n64=0;
        x=Wqkv=bqkv=Wb1=Wb2=temp=Wproj=nullptr;
        p768[0]=p768[1]=p768[2]=nullptr; p64[0]=p64[1]=nullptr;
        for (int i=0;i<n_in;i++){
            const float* p = (const float*)d_in[i];
            long sz = (long)in_sizes[i] / div;
            if ((long)in_sizes[i] % div) { sz = -1; }
            switch (sz){
                case 1572864: x=p; break;
                case 1769472: Wqkv=p; break;
                case 2304:    bqkv=p; break;
                case 98304:   Wb1=p; break;
                case 7680:    Wb2=p; break;
                case 1:       temp=p; break;
                case 589824:  Wproj=p; break;
                case 768:     if (n768<3) p768[n768++]=p; break;
                case 64:      if (n64<2)  p64[n64++]=p; break;
                default: break;
            }
        }
        if (x && Wqkv && bqkv && Wb1 && Wb2 && temp && Wproj && n768==3 && n64==2) break;
    }
    if (!x || !Wqkv || !bqkv || !Wb1 || !Wb2 || !temp || !Wproj || n768<3 || n64<2){
        x=(const float*)d_in[0]; Wqkv=(const float*)d_in[1]; bqkv=(const float*)d_in[2];
        Wb1=(const float*)d_in[3]; Wb2=(const float*)d_in[4]; temp=(const float*)d_in[5];
        Wproj=(const float*)d_in[6];
        p768[0]=(const float*)d_in[7]; p768[1]=(const float*)d_in[8]; p768[2]=(const float*)d_in[9];
        p64[0]=(const float*)d_in[10]; p64[1]=(const float*)d_in[11];
    }

    float* out = (float*)d_out;

    void *p_qkv, *p_gp, *p_gdum, *p_sc, *p_C, *p_zC;
    void *p_xnhi, *p_xnlo, *p_wqThi, *p_wqTlo, *p_wpThi, *p_wpTlo, *p_athi, *p_atlo;
    void *p_lng, *p_lnb, *p_bproj, *p_memg, *p_memb;
    cudaGetSymbolAddress(&p_qkv,  g_qkv);
    cudaGetSymbolAddress(&p_gp,   g_gp);
    cudaGetSymbolAddress(&p_gdum, g_gate_dummy);
    cudaGetSymbolAddress(&p_sc,   g_sc);
    cudaGetSymbolAddress(&p_C,    g_C);
    cudaGetSymbolAddress(&p_zC,   g_zC);
    cudaGetSymbolAddress(&p_xnhi, g_xnhi);  cudaGetSymbolAddress(&p_xnlo, g_xnlo);
    cudaGetSymbolAddress(&p_wqThi,g_wqThi); cudaGetSymbolAddress(&p_wqTlo,g_wqTlo);
    cudaGetSymbolAddress(&p_wpThi,g_wpThi); cudaGetSymbolAddress(&p_wpTlo,g_wpTlo);
    cudaGetSymbolAddress(&p_athi, g_athi);  cudaGetSymbolAddress(&p_atlo, g_atlo);
    cudaGetSymbolAddress(&p_lng,  g_lng);
    cudaGetSymbolAddress(&p_lnb,  g_lnb);
    cudaGetSymbolAddress(&p_bproj,g_bproj);
    cudaGetSymbolAddress(&p_memg, g_memg);
    cudaGetSymbolAddress(&p_memb, g_memb);

    float*  qkv  = (float*)p_qkv;
    float4* gp   = (float4*)p_gp;
    float*  gate_out = (out_size >= Mq*Dq + Mq*Hq) ? (out + (size_t)Mq*Dq)
                                                   : (float*)p_gdum;

    const int GEMM_SMEM = 2 * 4 * 128 * 40 * (int)sizeof(__nv_bfloat16);  // 81920
    static int init_done = 0;
    static cudaStream_t s2, s3;
    static cudaEvent_t evStart, evW, evP;
    if (!init_done){
        cudaFuncSetAttribute(hmma_gemm_combo, cudaFuncAttributeMaxDynamicSharedMemorySize, GEMM_SMEM);
        cudaStreamCreateWithFlags(&s2, cudaStreamNonBlocking);
        cudaStreamCreateWithFlags(&s3, cudaStreamNonBlocking);
        cudaEventCreateWithFlags(&evStart, cudaEventDisableTiming);
        cudaEventCreateWithFlags(&evW,     cudaEventDisableTiming);
        cudaEventCreateWithFlags(&evP,     cudaEventDisableTiming);
        init_done = 1;
    }

    // ---- fork: side streams join the (possibly capturing) default stream ----
    cudaEventRecord(evStart, 0);
    cudaStreamWaitEvent(s2, evStart, 0);
    cudaStreamWaitEvent(s3, evStart, 0);

    // stream2: weight transpose+split (independent of everything else)
    wsplitT2<<<dim3(96, Dq/32), dim3(32,8), 0, s2>>>(Wqkv, Wproj,
        (__nv_bfloat16*)p_wqThi, (__nv_bfloat16*)p_wqTlo,
        (__nv_bfloat16*)p_wpThi, (__nv_bfloat16*)p_wpTlo);
    cudaEventRecord(evW, s2);

    // stream3: bottleneck -> scan_pre (depends only on raw x/Wb1/Wb2/temp)
    bottleneck8<<<Mq/8, 256, 0, s3>>>(x, Wb1, Wb2, temp, gp, gate_out);
    scan_pre<<<Bq*Hq, Lq, 0, s3>>>(gp, (float4*)p_sc);
    cudaEventRecord(evP, s3);

    // main stream: route -> LN(x) -> QKV GEMM
    route_params_kernel<<<1, 256>>>(p768[0], p768[1], p768[2], p64[0], p64[1]);
    ln768_split<<<Mq, 256>>>(x, (const float*)p_lng, (const float*)p_lnb,
                             (__nv_bfloat16*)p_xnhi, (__nv_bfloat16*)p_xnlo);
    cudaStreamWaitEvent(0, evW, 0);
    hmma_gemm_combo<<<dim3(threeD/128, Mq/128), 512, GEMM_SMEM>>>(
        (const __nv_bfloat16*)p_xnhi, (const __nv_bfloat16*)p_xnlo,
        (const __nv_bfloat16*)p_wqThi, (const __nv_bfloat16*)p_wqTlo,
        bqkv, qkv, threeD, Dq, 2*Dq);

    // join: scan needs both qkv (main) and sc (stream3)
    cudaStreamWaitEvent(0, evP, 0);
    scan_chunk_acc<<<Bq*Hq*NC, 256>>>(qkv, (const float4*)p_sc, (float*)p_C, (float*)p_zC);
    scan_prefix<<<Bq*Hq, 256>>>((float*)p_C, (float*)p_zC);
    scan_chunk_out_ln<<<Bq*Hq*NC, 256>>>(qkv, (const float4*)p_sc,
                                         (const float*)p_C, (const float*)p_zC,
                                         (const float*)p_memg, (const float*)p_memb,
                                         (__nv_bfloat16*)p_athi, (__nv_bfloat16*)p_atlo);
    // out = attn @ Wproj + bproj
    hmma_gemm_combo<<<dim3(Dq/128, Mq/128), 512, GEMM_SMEM>>>(
        (const __nv_bfloat16*)p_athi, (const __nv_bfloat16*)p_atlo,
        (const __nv_bfloat16*)p_wpThi, (const __nv_bfloat16*)p_wpTlo,
        (const float*)p_bproj, out, Dq, Dq, 0);
}

// round 16
// speedup vs baseline: 1.2988x; 1.2988x over previous
#include <cuda_runtime.h>
#include <cuda_bf16.h>
#include <cstdint>
#include <cmath>

#define Bq 4
#define Lq 512
#define Dq 768
#define Hq 12
#define DHq 64
#define Rq 128
#define Mq (Bq*Lq)          // 2048
#define threeD (3*Dq)       // 2304
#define NC 8                // scan chunks
#define CL 64               // tokens per chunk
#define PI_F 3.14159265358979323846f

// ---------------- scratch (static __device__ — no allocation) ----------------
__device__ float  g_qkv  [Mq*threeD];
__device__ float4 g_gp   [Mq*Hq];
__device__ float  g_gate_dummy[Mq*Hq];

__device__ float4 g_sc [Bq*Hq*Lq];
__device__ float  g_C  [Bq*Hq*NC*DHq*DHq];
__device__ float  g_zC [Bq*Hq*NC*DHq];

__device__ __align__(16) __nv_bfloat16 g_xnhi[Mq*Dq],      g_xnlo[Mq*Dq];
__device__ __align__(16) __nv_bfloat16 g_wqThi[threeD*Dq], g_wqTlo[threeD*Dq];
__device__ __align__(16) __nv_bfloat16 g_wpThi[Dq*Dq],     g_wpTlo[Dq*Dq];
__device__ __align__(16) __nv_bfloat16 g_athi[Mq*Dq],      g_atlo[Mq*Dq];

__device__ __align__(16) float g_lng[Dq], g_lnb[Dq], g_bproj[Dq];
__device__ __align__(16) float g_memg[DHq], g_memb[DHq];

static __device__ __forceinline__ float sigmoidf_(float x){ return 1.f/(1.f+expf(-x)); }

static __device__ __forceinline__ uint32_t smem_u32(const void* p){
    uint32_t a;
    asm("{ .reg .u64 t; cvta.to.shared.u64 t, %1; cvt.u32.u64 %0, t; }" : "=r"(a) : "l"(p));
    return a;
}
static __device__ __forceinline__ void ldsm_x4(uint32_t addr, uint32_t* r){
    asm volatile("ldmatrix.sync.aligned.m8n8.x4.shared.b16 {%0,%1,%2,%3}, [%4];"
        : "=r"(r[0]), "=r"(r[1]), "=r"(r[2]), "=r"(r[3]) : "r"(addr));
}
static __device__ __forceinline__ void mma16816(float* d, const uint32_t* a, const uint32_t* b){
    asm volatile("mma.sync.aligned.m16n8k16.row.col.f32.bf16.bf16.f32 "
        "{%0,%1,%2,%3}, {%4,%5,%6,%7}, {%8,%9}, {%0,%1,%2,%3};"
        : "+f"(d[0]), "+f"(d[1]), "+f"(d[2]), "+f"(d[3])
        : "r"(a[0]), "r"(a[1]), "r"(a[2]), "r"(a[3]), "r"(b[0]), "r"(b[1]));
}

// ---------------- K0: fast route (2 barriers, shfl reductions) ----------------
__global__ void route_fast(const float* __restrict__ a0,
                           const float* __restrict__ a1,
                           const float* __restrict__ a2,
                           const float* __restrict__ c0,
                           const float* __restrict__ c1)
{
    int t = threadIdx.x;           // 256
    int lane = t & 31, warp = t >> 5;
    __shared__ float wsum[8][5];
    __shared__ int s_gi, s_mg;

    // issue all loads up front (latency overlapped)
    float v0[3], v1[3], v2[3];
#pragma unroll
    for (int i=0;i<3;i++){
        int idx = t + 256*i;
        v0[i] = a0[idx]; v1[i] = a1[idx]; v2[i] = a2[idx];
    }
    float w0 = 0.f, w1 = 0.f;
    if (t < DHq){ w0 = fabsf(c0[t]-1.f); w1 = fabsf(c1[t]-1.f); }

    float d0=0.f, d1=0.f, d2=0.f;
#pragma unroll
    for (int i=0;i<3;i++){
        d0 += fabsf(v0[i]-1.f); d1 += fabsf(v1[i]-1.f); d2 += fabsf(v2[i]-1.f);
    }
#pragma unroll
    for (int o=16;o>0;o>>=1){
        d0 += __shfl_xor_sync(0xffffffffu, d0, o);
        d1 += __shfl_xor_sync(0xffffffffu, d1, o);
        d2 += __shfl_xor_sync(0xffffffffu, d2, o);
        w0 += __shfl_xor_sync(0xffffffffu, w0, o);
        w1 += __shfl_xor_sync(0xffffffffu, w1, o);
    }
    if (lane == 0){
        wsum[warp][0]=d0; wsum[warp][1]=d1; wsum[warp][2]=d2;
        wsum[warp][3]=w0; wsum[warp][4]=w1;
    }
    __syncthreads();
    if (t == 0){
        float s[5] = {0,0,0,0,0};
#pragma unroll
        for (int w=0;w<8;w++)
#pragma unroll
            for (int j=0;j<5;j++) s[j] += wsum[w][j];
        s_gi = (s[0] <= s[1] && s[0] <= s[2]) ? 0 : ((s[1] <= s[2]) ? 1 : 2);
        s_mg = (s[3] <= s[4]) ? 0 : 1;
    }
    __syncthreads();
    int gi = s_gi, mg = s_mg;
    const float* arr[3] = {a0, a1, a2};
    int r0 = (gi == 0) ? 1 : 0;
    int r1 = (gi == 2) ? 1 : 2;
#pragma unroll
    for (int i=0;i<3;i++){
        int idx = t + 256*i;
        g_lng[idx]   = arr[gi][idx];
        g_bproj[idx] = arr[r0][idx];
        g_lnb[idx]   = arr[r1][idx];
    }
    if (t < DHq){
        g_memg[t] = mg ? c1[t] : c0[t];
        g_memb[t] = mg ? c0[t] : c1[t];
    }
}

// ---------------- K1: LN over 768, x cached in regs, bf16 hi/lo split out ----------------
__global__ void ln768_split(const float* __restrict__ x,
                            const float* __restrict__ g,
                            const float* __restrict__ b,
                            __nv_bfloat16* __restrict__ yhi,
                            __nv_bfloat16* __restrict__ ylo)
{
    int m = blockIdx.x;
    int t = threadIdx.x;  // 256
    __shared__ float sbuf[256];
    __shared__ float s_mu, s_rstd;
    const float* xr = x + (size_t)m*Dq;
    float v[3];
    float s = 0.f;
#pragma unroll
    for (int i=0;i<3;i++){ v[i] = xr[t + 256*i]; s += v[i]; }
    sbuf[t]=s; __syncthreads();
    for (int o=128;o>0;o>>=1){ if(t<o) sbuf[t]+=sbuf[t+o]; __syncthreads(); }
    if (t==0) s_mu = sbuf[0]*(1.f/Dq);
    __syncthreads();
    float mu = s_mu;
    float vv = 0.f;
#pragma unroll
    for (int i=0;i<3;i++){ float d=v[i]-mu; vv += d*d; }
    sbuf[t]=vv; __syncthreads();
    for (int o=128;o>0;o>>=1){ if(t<o) sbuf[t]+=sbuf[t+o]; __syncthreads(); }
    if (t==0) s_rstd = rsqrtf(sbuf[0]*(1.f/Dq) + 1e-5f);
    __syncthreads();
    float rstd = s_rstd;
#pragma unroll
    for (int i=0;i<3;i++){
        int idx = t + 256*i;
        float y = (v[i]-mu)*rstd*g[idx] + b[idx];
        __nv_bfloat16 hi = __float2bfloat16(y);
        __nv_bfloat16 lo = __float2bfloat16(y - __bfloat162float(hi));
        yhi[(size_t)m*Dq + idx] = hi;
        ylo[(size_t)m*Dq + idx] = lo;
    }
}

// ---------------- K1b: merged transpose+split for Wqkv and Wproj ----------------
__global__ void wsplitT2(const float* __restrict__ Wq, const float* __restrict__ Wp,
                         __nv_bfloat16* __restrict__ hiQ, __nv_bfloat16* __restrict__ loQ,
                         __nv_bfloat16* __restrict__ hiP, __nv_bfloat16* __restrict__ loP)
{
    __shared__ float t[32][33];
    int bx = blockIdx.x;
    const float* W; __nv_bfloat16 *Th, *Tl; int N, n0;
    if (bx < 72){ W = Wq; Th = hiQ; Tl = loQ; N = threeD; n0 = bx*32; }
    else        { W = Wp; Th = hiP; Tl = loP; N = Dq;     n0 = (bx-72)*32; }
    int k0 = blockIdx.y*32;
    int tx = threadIdx.x, ty = threadIdx.y;
#pragma unroll
    for (int j=0;j<4;j++){
        int k = k0 + ty + j*8;
        t[ty + j*8][tx] = W[(size_t)k*N + n0 + tx];
    }
    __syncthreads();
#pragma unroll
    for (int j=0;j<4;j++){
        int n = n0 + ty + j*8;
        float v = t[tx][ty + j*8];
        __nv_bfloat16 hi = __float2bfloat16(v);
        __nv_bfloat16 lo = __float2bfloat16(v - __bfloat162float(hi));
        Th[(size_t)n*Dq + k0 + tx] = hi;
        Tl[(size_t)n*Dq + k0 + tx] = lo;
    }
}

// ---------------- K2: HMMA combo GEMM, 512 threads, warp tile 32x32 (round-14) ----------------
__global__ __launch_bounds__(512) void hmma_gemm_combo(
    const __nv_bfloat16* __restrict__ Ahi, const __nv_bfloat16* __restrict__ Alo,
    const __nv_bfloat16* __restrict__ BhiT, const __nv_bfloat16* __restrict__ BloT,
    const float* __restrict__ bias, float* __restrict__ C,
    int Nn, int Kn, int eluCols)
{
    extern __shared__ __align__(16) __nv_bfloat16 dsm[];
    int tid = threadIdx.x, lane = tid&31, wid = tid>>5;
    int warp_m = wid & 3, warp_n = wid >> 2;
    int m0 = blockIdx.y*128, n0 = blockIdx.x*128;

    float acc[2][4][4];
#pragma unroll
    for (int i=0;i<2;i++)
#pragma unroll
        for (int j=0;j<4;j++)
#pragma unroll
            for (int q=0;q<4;q++) acc[i][j][q]=0.f;

    int kslabs = Kn/32;
    int srow = tid>>2, ssub = tid&3;

    const __nv_bfloat16* gAh = Ahi  + (size_t)(m0+srow)*Kn + ssub*8;
    const __nv_bfloat16* gAl = Alo  + (size_t)(m0+srow)*Kn + ssub*8;
    const __nv_bfloat16* gBh = BhiT + (size_t)(n0+srow)*Kn + ssub*8;
    const __nv_bfloat16* gBl = BloT + (size_t)(n0+srow)*Kn + ssub*8;

    uint4 pah = *(const uint4*)gAh;
    uint4 pal = *(const uint4*)gAl;
    uint4 pbh = *(const uint4*)gBh;
    uint4 pbl = *(const uint4*)gBl;

    int r7 = lane & 7, sel = lane >> 3;
    int soff = srow*40 + ssub*8;

    for (int s=0; s<kslabs; s++){
        int buf = s & 1;
        __nv_bfloat16* bb = dsm + buf*20480;
        *(uint4*)(bb + soff)         = pah;
        *(uint4*)(bb + 5120  + soff) = pal;
        *(uint4*)(bb + 10240 + soff) = pbh;
        *(uint4*)(bb + 15360 + soff) = pbl;
        __syncthreads();

        if (s+1 < kslabs){
            int kk = (s+1)*32;
            pah = *(const uint4*)(gAh + kk);
            pal = *(const uint4*)(gAl + kk);
            pbh = *(const uint4*)(gBh + kk);
            pbl = *(const uint4*)(gBl + kk);
        }

        __nv_bfloat16* sAh = bb;
        __nv_bfloat16* sAl = bb + 5120;
        __nv_bfloat16* sBh = bb + 10240;
        __nv_bfloat16* sBl = bb + 15360;

#pragma unroll
        for (int ks=0; ks<2; ks++){
            uint32_t aF[2][4], bFh[2][4], bFl[2][4];
            int acol = ks*16 + ((sel>>1)<<3);
            int bcol = ks*16 + ((sel&1)<<3);
#pragma unroll
            for (int am=0; am<2; am++){
                int row = warp_m*32 + am*16 + r7 + ((sel&1)<<3);
                ldsm_x4(smem_u32(sAh + row*40 + acol), aF[am]);
            }
#pragma unroll
            for (int p=0; p<2; p++){
                int row = warp_n*32 + p*16 + r7 + ((sel>>1)<<3);
                ldsm_x4(smem_u32(sBh + row*40 + bcol), bFh[p]);
                ldsm_x4(smem_u32(sBl + row*40 + bcol), bFl[p]);
            }
#pragma unroll
            for (int am=0; am<2; am++)
#pragma unroll
                for (int an=0; an<4; an++){
                    mma16816(acc[am][an], aF[am], &bFh[an>>1][(an&1)*2]);
                    mma16816(acc[am][an], aF[am], &bFl[an>>1][(an&1)*2]);
                }
#pragma unroll
            for (int am=0; am<2; am++){
                int row = warp_m*32 + am*16 + r7 + ((sel&1)<<3);
                ldsm_x4(smem_u32(sAl + row*40 + acol), aF[am]);
            }
#pragma unroll
            for (int am=0; am<2; am++)
#pragma unroll
                for (int an=0; an<4; an++)
                    mma16816(acc[am][an], aF[am], &bFh[an>>1][(an&1)*2]);
        }
    }

    int g = lane>>2, t4 = lane&3;
#pragma unroll
    for (int am=0; am<2; am++){
#pragma unroll
        for (int an=0; an<4; an++){
            int row = m0 + warp_m*32 + am*16 + g;
            int col = n0 + warp_n*32 + an*8 + t4*2;
            float b0 = bias[col], b1 = bias[col+1];
            float v0 = acc[am][an][0] + b0;
            float v1 = acc[am][an][1] + b1;
            float v2 = acc[am][an][2] + b0;
            float v3 = acc[am][an][3] + b1;
            if (col   < eluCols){ v0 = (v0>0.f)?(v0+1.f):expf(v0); v2 = (v2>0.f)?(v2+1.f):expf(v2); }
            if (col+1 < eluCols){ v1 = (v1>0.f)?(v1+1.f):expf(v1); v3 = (v3>0.f)?(v3+1.f):expf(v3); }
            *(float2*)(C + (size_t)row*Nn + col)     = make_float2(v0, v1);
            *(float2*)(C + (size_t)(row+8)*Nn + col) = make_float2(v2, v3);
        }
    }
}

// ---------------- K3: bottleneck, thread owns (token, 4 W1 cols) ----------------
__global__ __launch_bounds__(256) void bottleneck8(
    const float* __restrict__ x,  const float* __restrict__ W1,
    const float* __restrict__ W2, const float* __restrict__ T,
    float4* __restrict__ gp, float* __restrict__ gate_out)
{
    int m0 = blockIdx.x*8;
    int t = threadIdx.x;
    int tok = t >> 5, lane = t & 31;
    __shared__ float sx[8][Dq];
    __shared__ float sh[8][Rq];
    __shared__ float sp[8][Hq*5];

    const float* xr = x + (size_t)m0*Dq;
    float* sxf = &sx[0][0];
    for (int i=t; i<8*Dq; i+=256) sxf[i] = xr[i];
    __syncthreads();

    float a0=0.f, a1=0.f, a2=0.f, a3=0.f;
    const float4* w1v = (const float4*)W1;
    for (int k=0;k<Dq;k++){
        float xv = sx[tok][k];
        float4 w = w1v[(size_t)k*32 + lane];
        a0 = fmaf(xv, w.x, a0);
        a1 = fmaf(xv, w.y, a1);
        a2 = fmaf(xv, w.z, a2);
        a3 = fmaf(xv, w.w, a3);
    }
    int c0 = lane*4;
    sh[tok][c0+0] = a0*sigmoidf_(a0);
    sh[tok][c0+1] = a1*sigmoidf_(a1);
    sh[tok][c0+2] = a2*sigmoidf_(a2);
    sh[tok][c0+3] = a3*sigmoidf_(a3);
    __syncthreads();

    if (t < 240){
        int c = t % 60;
        int tb = (t/60)*2;
#pragma unroll
        for (int tt=0; tt<2; tt++){
            float a = 0.f;
            for (int j=0;j<Rq;j++) a = fmaf(sh[tb+tt][j], W2[(size_t)j*(Hq*5) + c], a);
            sp[tb+tt][c] = a;
        }
    }
    __syncthreads();

    if (t < 8*Hq){
        int tk = t / Hq, hh = t % Hq;
        float p0=sp[tk][hh*5+0], p1=sp[tk][hh*5+1], p2=sp[tk][hh*5+2];
        float p3=sp[tk][hh*5+3], p4=sp[tk][hh*5+4];
        float temp = fminf(fmaxf(T[0], 0.1f), 2.0f);
        float sem_amp = sigmoidf_(p0);
        float sem_ph  = tanhf(p1)*PI_F;
        float ctx_amp = sigmoidf_(p2);
        float ctx_ph  = tanhf(p3)*PI_F;
        float decay   = 0.5f + 0.49f*sigmoidf_(p4);
        float inter   = tanhf(sem_amp*ctx_amp*cosf(sem_ph - ctx_ph)) * temp;
        float gate    = sigmoidf_(inter);
        float ema     = 1.f - decay;
        float ld      = logf(decay + 1e-8f);
        gp[(size_t)(m0+tk)*Hq + hh] = make_float4((1.f+gate)*ema, ema, ld, 0.f);
        gate_out[(size_t)(m0+tk)*Hq + hh] = gate;
    }
}

// ---------------- P0: per-(b,h) cumulative log-decay (fp64 block scan) ----------------
__global__ __launch_bounds__(512) void scan_pre(
    const float4* __restrict__ gp, float4* __restrict__ sc)
{
    int bh = blockIdx.x;
    int b = bh / Hq, h = bh % Hq;
    int l = threadIdx.x;
    __shared__ double scs[Lq];
    float4 gv = gp[(size_t)(b*Lq + l)*Hq + h];
    scs[l] = (double)gv.z;
    __syncthreads();
    for (int o=1;o<Lq;o<<=1){
        double add = (l>=o) ? scs[l-o] : 0.0;
        __syncthreads();
        scs[l] += add;
        __syncthreads();
    }
    double cld = scs[l];
    if (cld < -85.0) cld = -85.0;
    float df  = expf((float)cld);
    float idf = expf((float)(-cld));
    sc[(size_t)bh*Lq + l] = make_float4(gv.x*idf, gv.y*idf, df, 0.f);
}

// ---------------- P1: chunk-local kv/z accumulation ----------------
__global__ __launch_bounds__(256) void scan_chunk_acc(
    const float* __restrict__ qkv, const float4* __restrict__ sc,
    float* __restrict__ Cbuf, float* __restrict__ zbuf)
{
    int blk = blockIdx.x;
    int bh = blk >> 3, c = blk & 7;
    int b = bh / Hq, h = bh % Hq;
    int t = threadIdx.x, g = t>>6, e = t&63;
    int l0 = c*CL;

    __shared__ float sk[2][2][64], sv[2][2][64];

    float kv[16];
#pragma unroll
    for (int i=0;i<16;i++) kv[i]=0.f;
    float z = 0.f;

    int sel = t >> 6, ee = t & 63;
    for (int it=0; it<CL/2; it++){
        int buf = it & 1;
        int l = l0 + it*2;
        {
            size_t base = ((size_t)(b*Lq + l + (sel&1)))*threeD + h*DHq;
            if (sel < 2) sk[buf][sel][ee]   = qkv[base + Dq   + ee];
            else         sv[buf][sel-2][ee] = qkv[base + 2*Dq + ee];
        }
        float4 s0 = sc[(size_t)bh*Lq + l];
        float4 s1 = sc[(size_t)bh*Lq + l+1];
        __syncthreads();
        float w0 = s0.x * sv[buf][0][e];
        float w1 = s1.x * sv[buf][1][e];
#pragma unroll
        for (int i=0;i<16;i++){
            int d = g*16 + i;
            kv[i] = fmaf(sk[buf][0][d], w0, kv[i]);
            kv[i] = fmaf(sk[buf][1][d], w1, kv[i]);
        }
        if (t < 64){
            z = fmaf(sk[buf][0][t], s0.y, z);
            z = fmaf(sk[buf][1][t], s1.y, z);
        }
    }
    float* Cp = Cbuf + (size_t)blk*(DHq*DHq);
#pragma unroll
    for (int i=0;i<16;i++) Cp[(g*16+i)*64 + e] = kv[i];
    if (t < 64) zbuf[(size_t)blk*DHq + t] = z;
}

// ---------------- P3: inline prefix + chunk replay + q readout + fused mem-LN ----------------
__global__ __launch_bounds__(256) void scan_chunk_out_ln(
    const float* __restrict__ qkv, const float4* __restrict__ sc,
    const float* __restrict__ Cbuf, const float* __restrict__ zbuf,
    const float* __restrict__ lg, const float* __restrict__ lb,
    __nv_bfloat16* __restrict__ yhi, __nv_bfloat16* __restrict__ ylo)
{
    int blk = blockIdx.x;
    int bh = blk >> 3, c = blk & 7;
    int b = bh / Hq, h = bh % Hq;
    int t = threadIdx.x, g = t>>6, e = t&63;
    int sec = t >> 6;
    int l0 = c*CL;

    __shared__ float sq[2][64], sk[2][64], sv[2][64];
    __shared__ float spart[2][4][64];
    __shared__ float sden[2][4][4];

    // inline exclusive prefix over chunks j < c (ascending order == old P2)
    float kv[16];
#pragma unroll
    for (int i=0;i<16;i++) kv[i] = 0.f;
    for (int j=0; j<c; j++){
        const float* Cp = Cbuf + (size_t)(bh*NC + j)*(DHq*DHq);
#pragma unroll
        for (int i=0;i<16;i++) kv[i] += Cp[(g*16+i)*64 + e];
    }
    float z[4];
#pragma unroll
    for (int i=0;i<4;i++) z[i] = 0.f;
    if (e < 4){
        int d0 = g*16 + e*4;
        for (int j=0; j<c; j++){
            const float* zp = zbuf + (size_t)(bh*NC + j)*DHq;
#pragma unroll
            for (int i=0;i<4;i++) z[i] += zp[d0 + i];
        }
    }

    float preA = 0.f, preB = 0.f;
    {
        size_t b0 = ((size_t)(b*Lq + l0  ))*threeD + h*DHq;
        size_t b1 = ((size_t)(b*Lq + l0+1))*threeD + h*DHq;
        if (t < 192){ preA = qkv[b0 + (size_t)sec*Dq + e]; preB = qkv[b1 + (size_t)sec*Dq + e]; }
    }
    float4 scA = sc[(size_t)bh*Lq + l0];
    float4 scB = sc[(size_t)bh*Lq + l0+1];

    for (int l=l0; l<l0+CL; l+=2){
        if      (t <  64){ sq[0][e] = preA; sq[1][e] = preB; }
        else if (t < 128){ sk[0][e] = preA; sk[1][e] = preB; }
        else if (t < 192){ sv[0][e] = preA; sv[1][e] = preB; }
        float wkA = scA.x, wzA = scA.y, dfA = scA.z;
        float wkB = scB.x, wzB = scB.y, dfB = scB.z;
        __syncthreads();                 // bar1

        if (l+2 < l0+CL){
            size_t bn0 = ((size_t)(b*Lq + l+2))*threeD + h*DHq;
            size_t bn1 = ((size_t)(b*Lq + l+3))*threeD + h*DHq;
            if (t < 192){ preA = qkv[bn0 + (size_t)sec*Dq + e]; preB = qkv[bn1 + (size_t)sec*Dq + e]; }
            scA = sc[(size_t)bh*Lq + l+2];
            scB = sc[(size_t)bh*Lq + l+3];
        }

        {
            float kvw = wkA * sv[0][e];
            float num = 0.f;
#pragma unroll
            for (int i=0;i<16;i++){
                int d = g*16 + i;
                kv[i] = fmaf(sk[0][d], kvw, kv[i]);
                num   = fmaf(sq[0][d], kv[i]*dfA, num);
            }
            spart[0][g][e] = num;
        }
        {
            float kvw = wkB * sv[1][e];
            float num = 0.f;
#pragma unroll
            for (int i=0;i<16;i++){
                int d = g*16 + i;
                kv[i] = fmaf(sk[1][d], kvw, kv[i]);
                num   = fmaf(sq[1][d], kv[i]*dfB, num);
            }
            spart[1][g][e] = num;
        }
        if (e < 4){
            int d0 = g*16 + e*4;
            float dA = 0.f, dB = 0.f;
#pragma unroll
            for (int i=0;i<4;i++){
                z[i] = fmaf(sk[0][d0+i], wzA, z[i]);
                dA   = fmaf(sq[0][d0+i], z[i]*dfA, dA);
            }
#pragma unroll
            for (int i=0;i<4;i++){
                z[i] = fmaf(sk[1][d0+i], wzB, z[i]);
                dB   = fmaf(sq[1][d0+i], z[i]*dfB, dB);
            }
            sden[0][g][e] = dA;
            sden[1][g][e] = dB;
        }
        __syncthreads();                 // bar2

        if (t < 64){
            int w = t >> 5;
            int lane = t & 31;
            float den = 1e-6f;
#pragma unroll
            for (int gg=0;gg<4;gg++)
#pragma unroll
                for (int jj=0;jj<4;jj++) den += sden[w][gg][jj];
            float y0 = (spart[w][0][lane]    + spart[w][1][lane]    + spart[w][2][lane]    + spart[w][3][lane])    / den;
            float y1 = (spart[w][0][lane+32] + spart[w][1][lane+32] + spart[w][2][lane+32] + spart[w][3][lane+32]) / den;
            float s = y0 + y1;
#pragma unroll
            for (int o=16;o>0;o>>=1) s += __shfl_xor_sync(0xffffffffu, s, o);
            float mu = s*(1.f/DHq);
            float d0 = y0-mu, d1 = y1-mu;
            float vv = d0*d0 + d1*d1;
#pragma unroll
            for (int o=16;o>0;o>>=1) vv += __shfl_xor_sync(0xffffffffu, vv, o);
            float rstd = rsqrtf(vv*(1.f/DHq) + 1e-5f);
            float o0 = d0*rstd*lg[lane]    + lb[lane];
            float o1 = d1*rstd*lg[lane+32] + lb[lane+32];
            size_t row = ((size_t)(b*Lq + l + w)*Hq + h)*DHq;
            __nv_bfloat16 h0 = __float2bfloat16(o0);
            __nv_bfloat16 h1 = __float2bfloat16(o1);
            yhi[row + lane]    = h0;
            yhi[row + lane+32] = h1;
            ylo[row + lane]    = __float2bfloat16(o0 - __bfloat162float(h0));
            ylo[row + lane+32] = __float2bfloat16(o1 - __bfloat162float(h1));
        }
    }
}

// ---------------- launch (single stream) ----------------
extern "C" void kernel_launch(void* const* d_in, const int* in_sizes, int n_in,
                              void* d_out, int out_size)
{
    const float* x=nullptr; const float* Wqkv=nullptr; const float* bqkv=nullptr;
    const float* Wb1=nullptr; const float* Wb2=nullptr; const float* temp=nullptr;
    const float* Wproj=nullptr;
    const float* p768[3]={nullptr,nullptr,nullptr}; int n768=0;
    const float* p64[2]={nullptr,nullptr};          int n64=0;

    for (int pass=0; pass<2; pass++){
        int div = (pass==0) ? 1 : 4;
        n768=0; n64=0;
        x=Wqkv=bqkv=Wb1=Wb2=temp=Wproj=nullptr;
        p768[0]=p768[1]=p768[2]=nullptr; p64[0]=p64[1]=nullptr;
        for (int i=0;i<n_in;i++){
            const float* p = (const float*)d_in[i];
            long sz = (long)in_sizes[i] / div;
            if ((long)in_sizes[i] % div) { sz = -1; }
            switch (sz){
                case 1572864: x=p; break;
                case 1769472: Wqkv=p; break;
                case 2304:    bqkv=p; break;
                case 98304:   Wb1=p; break;
                case 7680:    Wb2=p; break;
                case 1:       temp=p; break;
                case 589824:  Wproj=p; break;
                case 768:     if (n768<3) p768[n768++]=p; break;
                case 64:      if (n64<2)  p64[n64++]=p; break;
                default: break;
            }
        }
        if (x && Wqkv && bqkv && Wb1 && Wb2 && temp && Wproj && n768==3 && n64==2) break;
    }
    if (!x || !Wqkv || !bqkv || !Wb1 || !Wb2 || !temp || !Wproj || n768<3 || n64<2){
        x=(const float*)d_in[0]; Wqkv=(const float*)d_in[1]; bqkv=(const float*)d_in[2];
        Wb1=(const float*)d_in[3]; Wb2=(const float*)d_in[4]; temp=(const float*)d_in[5];
        Wproj=(const float*)d_in[6];
        p768[0]=(const float*)d_in[7]; p768[1]=(const float*)d_in[8]; p768[2]=(const float*)d_in[9];
        p64[0]=(const float*)d_in[10]; p64[1]=(const float*)d_in[11];
    }

    float* out = (float*)d_out;

    void *p_qkv, *p_gp, *p_gdum, *p_sc, *p_C, *p_zC;
    void *p_xnhi, *p_xnlo, *p_wqThi, *p_wqTlo, *p_wpThi, *p_wpTlo, *p_athi, *p_atlo;
    void *p_lng, *p_lnb, *p_bproj, *p_memg, *p_memb;
    cudaGetSymbolAddress(&p_qkv,  g_qkv);
    cudaGetSymbolAddress(&p_gp,   g_gp);
    cudaGetSymbolAddress(&p_gdum, g_gate_dummy);
    cudaGetSymbolAddress(&p_sc,   g_sc);
    cudaGetSymbolAddress(&p_C,    g_C);
    cudaGetSymbolAddress(&p_zC,   g_zC);
    cudaGetSymbolAddress(&p_xnhi, g_xnhi);  cudaGetSymbolAddress(&p_xnlo, g_xnlo);
    cudaGetSymbolAddress(&p_wqThi,g_wqThi); cudaGetSymbolAddress(&p_wqTlo,g_wqTlo);
    cudaGetSymbolAddress(&p_wpThi,g_wpThi); cudaGetSymbolAddress(&p_wpTlo,g_wpTlo);
    cudaGetSymbolAddress(&p_athi, g_athi);  cudaGetSymbolAddress(&p_atlo, g_atlo);
    cudaGetSymbolAddress(&p_lng,  g_lng);
    cudaGetSymbolAddress(&p_lnb,  g_lnb);
    cudaGetSymbolAddress(&p_bproj,g_bproj);
    cudaGetSymbolAddress(&p_memg, g_memg);
    cudaGetSymbolAddress(&p_memb, g_memb);

    float*  qkv  = (float*)p_qkv;
    float4* gp   = (float4*)p_gp;
    float*  gate_out = (out_size >= Mq*Dq + Mq*Hq) ? (out + (size_t)Mq*Dq)
                                                   : (float*)p_gdum;

    const int GEMM_SMEM = 2 * 4 * 128 * 40 * (int)sizeof(__nv_bfloat16);  // 81920
    static int smem_set = 0;
    if (!smem_set){
        cudaFuncSetAttribute(hmma_gemm_combo, cudaFuncAttributeMaxDynamicSharedMemorySize, GEMM_SMEM);
        smem_set = 1;
    }

    // 0) fast route
    route_fast<<<1, 256>>>(p768[0], p768[1], p768[2], p64[0], p64[1]);
    // 1) LN(x) -> bf16 hi/lo
    ln768_split<<<Mq, 256>>>(x, (const float*)p_lng, (const float*)p_lnb,
                             (__nv_bfloat16*)p_xnhi, (__nv_bfloat16*)p_xnlo);
    // 1b) merged weight transpose + split (Wqkv + Wproj)
    wsplitT2<<<dim3(96, Dq/32), dim3(32,8)>>>(Wqkv, Wproj,
        (__nv_bfloat16*)p_wqThi, (__nv_bfloat16*)p_wqTlo,
        (__nv_bfloat16*)p_wpThi, (__nv_bfloat16*)p_wpTlo);
    // 2) qkv = xn @ Wqkv + b (combo HMMA, 512 threads), elu+1 on cols<1536
    hmma_gemm_combo<<<dim3(threeD/128, Mq/128), 512, GEMM_SMEM>>>(
        (const __nv_bfloat16*)p_xnhi, (const __nv_bfloat16*)p_xnlo,
        (const __nv_bfloat16*)p_wqThi, (const __nv_bfloat16*)p_wqTlo,
        bqkv, qkv, threeD, Dq, 2*Dq);
    // 3) bottleneck gating
    bottleneck8<<<Mq/8, 256>>>(x, Wb1, Wb2, temp, gp, gate_out);
    // 4) chunked scan (P2 folded into P3)
    scan_pre<<<Bq*Hq, Lq>>>(gp, (float4*)p_sc);
    scan_chunk_acc<<<Bq*Hq*NC, 256>>>(qkv, (const float4*)p_sc, (float*)p_C, (float*)p_zC);
    scan_chunk_out_ln<<<Bq*Hq*NC, 256>>>(qkv, (const float4*)p_sc,
                                         (const float*)p_C, (const float*)p_zC,
                                         (const float*)p_memg, (const float*)p_memb,
                                         (__nv_bfloat16*)p_athi, (__nv_bfloat16*)p_atlo);
    // 6) out = attn @ Wproj + bproj (combo HMMA, 512 threads)
    hmma_gemm_combo<<<dim3(Dq/128, Mq/128), 512, GEMM_SMEM>>>(
        (const __nv_bfloat16*)p_athi, (const __nv_bfloat16*)p_atlo,
        (const __nv_bfloat16*)p_wpThi, (const __nv_bfloat16*)p_wpTlo,
        (const float*)p_bproj, out, Dq, Dq, 0);
}